// round 1
// baseline (speedup 1.0000x reference)
#include <cuda_runtime.h>
#include <math_constants.h>
#include <cstdint>

// KNN_18614388261211 — farthest-k selection (reference uses topk(largest=False) on -dist^2)
// x: (8, 2048, 3) f32 -> BN = 16384 points in 3D, k = 16 (k+1 = 17 selected, rank 0 dropped)
// out: [ dists (BN*16 f32, = pair values) | idx (BN*16, written as f32) ]

#define BN       16384
#define KOUT     16
#define NW       16               // warps per block
#define NTHREADS (NW * 32)
#define NBLOCKS  152              // GB300: 152 SMs, 1 CTA/SM (192KB smem)
#define TOTALW   (NBLOCKS * NW)
#define SMEM_BYTES (BN * 3 * 4)   // 192 KB: float2 xy[BN] + float z[BN]

__global__ __launch_bounds__(NTHREADS, 1)
void knn_kernel(const float* __restrict__ x, float* __restrict__ out) {
    extern __shared__ float smem[];
    float2* __restrict__ sxy = reinterpret_cast<float2*>(smem); // [BN]
    float*  __restrict__ sz  = smem + 2 * BN;                   // [BN]

    // Cooperative load of all points into SMEM (SoA: xy as float2, z scalar)
    for (int p = threadIdx.x; p < BN; p += NTHREADS) {
        float a = x[3 * p + 0];
        float b = x[3 * p + 1];
        float c = x[3 * p + 2];
        sxy[p] = make_float2(a, b);
        sz[p]  = c;
    }
    __syncthreads();

    const int lane = threadIdx.x & 31;
    const int gw   = blockIdx.x * NW + (threadIdx.x >> 5);
    const unsigned FULL = 0xffffffffu;

    for (int row = gw; row < BN; row += TOTALW) {
        const float2 pxy = sxy[row];
        const float  pz  = sz[row];
        // sq_i = ((x*x + y*y) + z*z), left-assoc, no fma (match XLA reduce order)
        const float sqi = __fadd_rn(__fadd_rn(__fmul_rn(pxy.x, pxy.x),
                                              __fmul_rn(pxy.y, pxy.y)),
                                    __fmul_rn(pz, pz));

        // Warp-distributed sorted list (ascending pair value == descending dist^2).
        // Lane l (0..16) holds rank-l element; lanes 17..31 hold +INF sentinels.
        float lv = CUDART_INF_F;
        int   lj = 0x7fffffff;
        float T  = CUDART_INF_F;   // broadcast copy of lane 16's value (threshold)
        int   Ti = 0x7fffffff;

        for (int j = lane; j < BN; j += 32) {
            const float2 q  = sxy[j];
            const float  qz = sz[j];
            // dot = ((px*qx + py*qy) + pz*qz), no fma
            const float dot = __fadd_rn(__fadd_rn(__fmul_rn(pxy.x, q.x),
                                                  __fmul_rn(pxy.y, q.y)),
                                        __fmul_rn(pz, qz));
            const float sqj = __fadd_rn(__fadd_rn(__fmul_rn(q.x, q.x),
                                                  __fmul_rn(q.y, q.y)),
                                        __fmul_rn(qz, qz));
            // pair = ((2*dot - sq_i) - sq_j)  (matches reference expression tree)
            const float pv = __fsub_rn(__fsub_rn(__fadd_rn(dot, dot), sqi), sqj);

            // Qualify against threshold (composite order: value asc, index asc on ties)
            const bool qual = (pv < T) || (pv == T && j < Ti);
            unsigned qm = __ballot_sync(FULL, qual);
            if (qm) {
                do {
                    const int src = __ffs(qm) - 1;
                    qm &= qm - 1;
                    const float nv = __shfl_sync(FULL, pv, src);
                    const int   nj = __shfl_sync(FULL, j,  src);
                    // Insert (nv,nj) into the distributed sorted list.
                    const bool after = (lane <= 16) &&
                                       ((lv > nv) || (lv == nv && lj > nj));
                    const unsigned im = __ballot_sync(FULL, after) & 0x1ffffu;
                    const float upv = __shfl_up_sync(FULL, lv, 1);
                    const int   upj = __shfl_up_sync(FULL, lj, 1);
                    if (im) {
                        const int pos = __ffs(im) - 1;
                        if (lane <= 16) {
                            if (lane > pos)        { lv = upv; lj = upj; }
                            else if (lane == pos)  { lv = nv;  lj = nj;  }
                        }
                    }
                } while (qm);
                T  = __shfl_sync(FULL, lv, 16);
                Ti = __shfl_sync(FULL, lj, 16);
            }
        }

        // Ranks 1..16 are the output (rank 0 = farthest point is dropped by reference).
        if (lane >= 1 && lane <= 16) {
            out[(size_t)row * KOUT + (lane - 1)] = lv;                       // dists (= pair)
            out[(size_t)BN * KOUT + (size_t)row * KOUT + (lane - 1)] =
                (float)lj;                                                    // idx as f32
        }
    }
}

extern "C" void kernel_launch(void* const* d_in, const int* in_sizes, int n_in,
                              void* d_out, int out_size) {
    const float* x = (const float*)d_in[0];
    float* out = (float*)d_out;
    cudaFuncSetAttribute(knn_kernel, cudaFuncAttributeMaxDynamicSharedMemorySize,
                         SMEM_BYTES);
    knn_kernel<<<NBLOCKS, NTHREADS, SMEM_BYTES>>>(x, out);
}